// round 11
// baseline (speedup 1.0000x reference)
#include <cuda_runtime.h>
#include <cuda_fp16.h>

// Problem constants (B,H,N,D,W) = (2,12,2048,128,64)
#define Bb 2
#define Hh 12
#define Nn 2048
#define Dd 128
#define Ww 64

#define BH      (Bb * Hh)          // 24
#define ROWS    (BH * Nn)          // 49152 query rows
#define ROW_U4  (Dd / 8)           // 16 x uint4 (8 fp16 = 16B) per 256B row
#define TOTAL_U4 (ROWS * ROW_U4)

#define NUM_SM   148
#define QB_TOTAL (ROWS / 8)        // 6144 query-blocks (8 queries / CTA, 1 per warp)
#define QB_PER_SM 42

// fp16 copies of K and V (device-global scratch; no runtime allocation)
__device__ uint4 g_k16[TOTAL_U4];
__device__ uint4 g_v16[TOTAL_U4];

__device__ __forceinline__ unsigned pack2(float x, float y) {
    __half2 h = __floats2half2_rn(x, y);
    return *reinterpret_cast<unsigned*>(&h);
}

// ---------------------------------------------------------------------------
// Kernel 1: convert K,V fp32 -> fp16. Each thread: 2 float4 in, 1 uint4 out.
// ---------------------------------------------------------------------------
__global__ void __launch_bounds__(256) cvt_kernel(const float4* __restrict__ k,
                                                  const float4* __restrict__ v) {
    int i = blockIdx.x * blockDim.x + threadIdx.x;
    if (i >= TOTAL_U4) return;
    float4 a0 = k[2 * i], a1 = k[2 * i + 1];
    uint4 u;
    u.x = pack2(a0.x, a0.y); u.y = pack2(a0.z, a0.w);
    u.z = pack2(a1.x, a1.y); u.w = pack2(a1.z, a1.w);
    g_k16[i] = u;
    float4 b0 = v[2 * i], b1 = v[2 * i + 1];
    u.x = pack2(b0.x, b0.y); u.y = pack2(b0.z, b0.w);
    u.z = pack2(b1.x, b1.y); u.w = pack2(b1.z, b1.w);
    g_v16[i] = u;
}

__device__ __forceinline__ float2 h2f2(unsigned u) {
    return __half22float2(*reinterpret_cast<const __half2*>(&u));
}

// Generic butterfly fold step: p has 2H live entries; lanes with hi==true own
// the top half. After the step, p[0..H) holds pairwise-reduced entries.
template <int H, int MASK>
__device__ __forceinline__ void fold_step(float* p, bool hi) {
#pragma unroll
    for (int i = 0; i < H; ++i) {
        float keep = hi ? p[i + H] : p[i];
        float send = hi ? p[i] : p[i + H];
        p[i] = keep + __shfl_xor_sync(0xffffffffu, send, MASK);
    }
}

// dot of 8 fp16 (one uint4) against qv[0..8)
__device__ __forceinline__ float dot8(uint4 a, const float* qv) {
    float2 f;
    f = h2f2(a.x);
    float s0 = qv[0] * f.x, s1 = qv[1] * f.y;
    f = h2f2(a.y);
    s0 = fmaf(qv[2], f.x, s0); s1 = fmaf(qv[3], f.y, s1);
    f = h2f2(a.z);
    s0 = fmaf(qv[4], f.x, s0); s1 = fmaf(qv[5], f.y, s1);
    f = h2f2(a.w);
    s0 = fmaf(qv[6], f.x, s0); s1 = fmaf(qv[7], f.y, s1);
    return s0 + s1;
}

__device__ __forceinline__ void accum16(float* acc, uint4 a, uint4 b, float pw) {
    float2 f;
    f = h2f2(a.x); acc[0]  = fmaf(pw, f.x, acc[0]);  acc[1]  = fmaf(pw, f.y, acc[1]);
    f = h2f2(a.y); acc[2]  = fmaf(pw, f.x, acc[2]);  acc[3]  = fmaf(pw, f.y, acc[3]);
    f = h2f2(a.z); acc[4]  = fmaf(pw, f.x, acc[4]);  acc[5]  = fmaf(pw, f.y, acc[5]);
    f = h2f2(a.w); acc[6]  = fmaf(pw, f.x, acc[6]);  acc[7]  = fmaf(pw, f.y, acc[7]);
    f = h2f2(b.x); acc[8]  = fmaf(pw, f.x, acc[8]);  acc[9]  = fmaf(pw, f.y, acc[9]);
    f = h2f2(b.y); acc[10] = fmaf(pw, f.x, acc[10]); acc[11] = fmaf(pw, f.y, acc[11]);
    f = h2f2(b.z); acc[12] = fmaf(pw, f.x, acc[12]); acc[13] = fmaf(pw, f.y, acc[13]);
    f = h2f2(b.w); acc[14] = fmaf(pw, f.x, acc[14]); acc[15] = fmaf(pw, f.y, acc[15]);
}

// One score pass over 32 columns. Lane = (grp in 0..3, sub in 0..7).
// Slot s: group g handles column 4*s+g; its 8 lanes cooperatively load the
// 256B K row (each lane 32B = 2 x LDG.128) and compute a 16-dim partial.
// 3-step fold within 8-lane groups -> lane (grp,sub) returns the full score
// of column 4*sub + grp.
__device__ __forceinline__ float score_pass(const uint4* __restrict__ kb,
                                            int c, const float* qv,
                                            int grp, int sub) {
    float p[8];
#pragma unroll
    for (int s = 0; s < 8; ++s) {
        int col = __shfl_sync(0xffffffffu, c, 4 * s + grp);
        const uint4* r = kb + col * ROW_U4;
        uint4 a = r[0];
        uint4 b = r[1];
        p[s] = dot8(a, qv) + dot8(b, qv + 8);
    }
    fold_step<4, 4>(p, (sub & 4) != 0);
    fold_step<2, 2>(p, (sub & 2) != 0);
    fold_step<1, 1>(p, (sub & 1) != 0);
    return p[0];
}

// ---------------------------------------------------------------------------
// Kernel 2: attention. One warp per query; 8 warps/CTA. Block->query swizzle
// keeps each SM inside one (b,h)'s 1MB fp16 K/V working set for L1 reuse.
// ---------------------------------------------------------------------------
__global__ void __launch_bounds__(256, 3) attn_kernel(const float* __restrict__ q,
                                                      const int* __restrict__ col_ids,
                                                      float* __restrict__ out) {
    int qb = (int)(blockIdx.x % NUM_SM) * QB_PER_SM + (int)(blockIdx.x / NUM_SM);
    if (qb >= QB_TOTAL) return;

    const int warp = threadIdx.x >> 5;
    const unsigned lane = threadIdx.x & 31u;
    const int sub = lane & 7;       // dim chunk: dims [16*sub, 16*sub+16)
    const int grp = lane >> 3;      // column subgroup 0..3
    const int g = qb * 8 + warp;    // global query row
    const int n = g & (Nn - 1);     // sequence position (col_ids row)
    const int bh = g >> 11;         // b*H + h
    const unsigned FULL = 0xffffffffu;

    const uint4* __restrict__ kb = g_k16 + (size_t)bh * (Nn * ROW_U4) + sub * 2;
    const uint4* __restrict__ vb = g_v16 + (size_t)bh * (Nn * ROW_U4) + sub * 2;

    // q: lane owns dims [16*sub, 16*sub+16)
    const float4* qrow = reinterpret_cast<const float4*>(q) + (size_t)g * 32;
    float qv[16];
#pragma unroll
    for (int i = 0; i < 4; ++i) {
        float4 t = qrow[sub * 4 + i];
        qv[4 * i + 0] = t.x; qv[4 * i + 1] = t.y;
        qv[4 * i + 2] = t.z; qv[4 * i + 3] = t.w;
    }

    const int* crow = col_ids + n * Ww;
    const int c0 = crow[lane];         // lane l holds column index l
    const int c1 = crow[lane + 32];    // and column l+32

    // ---- scores: lane (grp,sub) ends with cols 4*sub+grp and 32+4*sub+grp ----
    float sA = score_pass(kb, c0, qv, grp, sub);
    float sB = score_pass(kb, c1, qv, grp, sub);

    // ---- softmax over 64 values distributed 2/lane (order-agnostic) ----
    const float scale = 0.08838834764831843f;   // 1/sqrt(128)
    float a = sA * scale;
    float b = sB * scale;
    float mx = fmaxf(a, b);
#pragma unroll
    for (int o = 16; o > 0; o >>= 1) mx = fmaxf(mx, __shfl_xor_sync(FULL, mx, o));
    const float eA = __expf(a - mx);
    const float eB = __expf(b - mx);
    float sm = eA + eB;
#pragma unroll
    for (int o = 16; o > 0; o >>= 1) sm += __shfl_xor_sync(FULL, sm, o);
    const float inv = __fdividef(1.0f, sm);
    const float pA = eA * inv;   // prob of column 4*sub+grp
    const float pB = eB * inv;   // prob of column 32+4*sub+grp

    // ---- output: group g accumulates columns {4j+g}, lane owns 16 dims ----
    float acc[16];
#pragma unroll
    for (int i = 0; i < 16; ++i) acc[i] = 0.f;

#pragma unroll
    for (int j = 0; j < 8; ++j) {
        float pw = __shfl_sync(FULL, pA, grp * 8 + j);   // prob of col 4j+grp
        int col  = __shfl_sync(FULL, c0, 4 * j + grp);   // its column index
        const uint4* r = vb + col * ROW_U4;
        uint4 va = r[0];
        uint4 vb4 = r[1];
        accum16(acc, va, vb4, pw);
    }
#pragma unroll
    for (int j = 0; j < 8; ++j) {
        float pw = __shfl_sync(FULL, pB, grp * 8 + j);   // prob of col 32+4j+grp
        int col  = __shfl_sync(FULL, c1, 4 * j + grp);
        const uint4* r = vb + col * ROW_U4;
        uint4 va = r[0];
        uint4 vb4 = r[1];
        accum16(acc, va, vb4, pw);
    }

    // Reduce the 4 groups' partials (same dims at same sub, different grp).
    // Fold halves the dims kept per lane each step: after both steps lane
    // (grp,sub) holds 4 fully-summed dims starting at 16*sub + 8*(grp&1) + 4*(grp>>1).
    fold_step<8, 8>(acc, (grp & 1) != 0);
    fold_step<4, 16>(acc, (grp & 2) != 0);

    const int u4idx = 4 * sub + 2 * (grp & 1) + (grp >> 1);  // bijection over 32 lanes
    reinterpret_cast<float4*>(out)[(size_t)g * 32 + u4idx] =
        make_float4(acc[0], acc[1], acc[2], acc[3]);
}

// ---------------------------------------------------------------------------
// Launch. Inputs (metadata order): q f32, k f32, v f32, col_ids i32. Out f32.
// ---------------------------------------------------------------------------
extern "C" void kernel_launch(void* const* d_in, const int* in_sizes, int n_in,
                              void* d_out, int out_size) {
    const float* q = (const float*)d_in[0];
    const float* k = (const float*)d_in[1];
    const float* v = (const float*)d_in[2];
    const int* col = (const int*)d_in[3];
    float* out = (float*)d_out;

    (void)cudaFuncSetAttribute(attn_kernel,
                               cudaFuncAttributePreferredSharedMemoryCarveout,
                               cudaSharedmemCarveoutMaxL1);

    cvt_kernel<<<(TOTAL_U4 + 255) / 256, 256>>>((const float4*)k, (const float4*)v);
    attn_kernel<<<NUM_SM * QB_PER_SM, 256>>>(q, col, out);
}

// round 12
// speedup vs baseline: 1.9696x; 1.9696x over previous
#include <cuda_runtime.h>
#include <cuda_fp16.h>

// Problem constants (B,H,N,D,W) = (2,12,2048,128,64)
#define Bb 2
#define Hh 12
#define Nn 2048
#define Dd 128
#define Ww 64

#define BH      (Bb * Hh)          // 24
#define ROWS    (BH * Nn)          // 49152 query rows
#define ROW_U4  (Dd / 8)           // 16 x uint4 (8 fp16 = 16B) per 256B row
#define TOTAL_U4 (ROWS * ROW_U4)

#define NUM_SM   148
#define QB_TOTAL (ROWS / 8)        // 6144 query-blocks (8 queries / CTA, 1 per warp)
#define QB_PER_SM 42

// fp16 copies of K and V (device-global scratch; no runtime allocation)
__device__ uint4 g_k16[TOTAL_U4];
__device__ uint4 g_v16[TOTAL_U4];

__device__ __forceinline__ unsigned pack2(float x, float y) {
    __half2 h = __floats2half2_rn(x, y);
    return *reinterpret_cast<unsigned*>(&h);
}

// ---------------------------------------------------------------------------
// Kernel 1: convert K,V fp32 -> fp16. Each thread: 2 float4 in, 1 uint4 out.
// ---------------------------------------------------------------------------
__global__ void __launch_bounds__(256) cvt_kernel(const float4* __restrict__ k,
                                                  const float4* __restrict__ v) {
    int i = blockIdx.x * blockDim.x + threadIdx.x;
    if (i >= TOTAL_U4) return;
    float4 a0 = k[2 * i], a1 = k[2 * i + 1];
    uint4 u;
    u.x = pack2(a0.x, a0.y); u.y = pack2(a0.z, a0.w);
    u.z = pack2(a1.x, a1.y); u.w = pack2(a1.z, a1.w);
    g_k16[i] = u;
    float4 b0 = v[2 * i], b1 = v[2 * i + 1];
    u.x = pack2(b0.x, b0.y); u.y = pack2(b0.z, b0.w);
    u.z = pack2(b1.x, b1.y); u.w = pack2(b1.z, b1.w);
    g_v16[i] = u;
}

__device__ __forceinline__ float2 h2f2(unsigned u) {
    return __half22float2(*reinterpret_cast<const __half2*>(&u));
}

// Butterfly fold step: p has 2H live entries; lanes with hi==true own the top
// half. After the step, p[0..H) holds pairwise-reduced entries.
template <int H, int MASK>
__device__ __forceinline__ void fold_step(float* p, bool hi) {
#pragma unroll
    for (int i = 0; i < H; ++i) {
        float keep = hi ? p[i + H] : p[i];
        float send = hi ? p[i] : p[i + H];
        p[i] = keep + __shfl_xor_sync(0xffffffffu, send, MASK);
    }
}

// dot of 8 fp16 (one uint4) against qv[0..8)
__device__ __forceinline__ float dot8(uint4 a, const float* qv) {
    float2 f;
    f = h2f2(a.x);
    float s0 = qv[0] * f.x, s1 = qv[1] * f.y;
    f = h2f2(a.y);
    s0 = fmaf(qv[2], f.x, s0); s1 = fmaf(qv[3], f.y, s1);
    f = h2f2(a.z);
    s0 = fmaf(qv[4], f.x, s0); s1 = fmaf(qv[5], f.y, s1);
    f = h2f2(a.w);
    s0 = fmaf(qv[6], f.x, s0); s1 = fmaf(qv[7], f.y, s1);
    return s0 + s1;
}

__device__ __forceinline__ void accum16(float* acc, uint4 a, uint4 b, float pw) {
    float2 f;
    f = h2f2(a.x); acc[0]  = fmaf(pw, f.x, acc[0]);  acc[1]  = fmaf(pw, f.y, acc[1]);
    f = h2f2(a.y); acc[2]  = fmaf(pw, f.x, acc[2]);  acc[3]  = fmaf(pw, f.y, acc[3]);
    f = h2f2(a.z); acc[4]  = fmaf(pw, f.x, acc[4]);  acc[5]  = fmaf(pw, f.y, acc[5]);
    f = h2f2(a.w); acc[6]  = fmaf(pw, f.x, acc[6]);  acc[7]  = fmaf(pw, f.y, acc[7]);
    f = h2f2(b.x); acc[8]  = fmaf(pw, f.x, acc[8]);  acc[9]  = fmaf(pw, f.y, acc[9]);
    f = h2f2(b.y); acc[10] = fmaf(pw, f.x, acc[10]); acc[11] = fmaf(pw, f.y, acc[11]);
    f = h2f2(b.z); acc[12] = fmaf(pw, f.x, acc[12]); acc[13] = fmaf(pw, f.y, acc[13]);
    f = h2f2(b.w); acc[14] = fmaf(pw, f.x, acc[14]); acc[15] = fmaf(pw, f.y, acc[15]);
}

// One score pass over 32 columns. Lane = (grp in 0..3, sub in 0..7).
// Slot s: group g handles column 4*s+g. Lane `sub` loads uint4 `row + sub`
// (bytes [16*sub,16*sub+16) -- the 8 lanes tile line 0 of the 256B row
// contiguously) and `row + 8 + sub` (line 1). Every LDG.128 covers 4 full
// 128B lines across the warp -> 2 wavefronts per gathered row (optimal).
// 3-step fold within 8-lane groups -> lane (grp,sub) returns the score of
// column 4*sub + grp.
__device__ __forceinline__ float score_pass(const uint4* __restrict__ kb,
                                            int c, const float* qv,
                                            int grp, int sub) {
    float p[8];
#pragma unroll
    for (int s = 0; s < 8; ++s) {
        int col = __shfl_sync(0xffffffffu, c, 4 * s + grp);
        const uint4* r = kb + col * ROW_U4;
        uint4 a = r[0];     // dims [8*sub, 8*sub+8)
        uint4 b = r[8];     // dims [64+8*sub, 64+8*sub+8)
        p[s] = dot8(a, qv) + dot8(b, qv + 8);
    }
    fold_step<4, 4>(p, (sub & 4) != 0);
    fold_step<2, 2>(p, (sub & 2) != 0);
    fold_step<1, 1>(p, (sub & 1) != 0);
    return p[0];
}

// ---------------------------------------------------------------------------
// Kernel 2: attention. One warp per query; 8 warps/CTA. Block->query swizzle
// keeps each SM inside one (b,h)'s 1MB fp16 K/V working set for L1 reuse.
// ---------------------------------------------------------------------------
__global__ void __launch_bounds__(256, 3) attn_kernel(const float* __restrict__ q,
                                                      const int* __restrict__ col_ids,
                                                      float* __restrict__ out) {
    int qb = (int)(blockIdx.x % NUM_SM) * QB_PER_SM + (int)(blockIdx.x / NUM_SM);
    if (qb >= QB_TOTAL) return;

    const int warp = threadIdx.x >> 5;
    const unsigned lane = threadIdx.x & 31u;
    const int sub = lane & 7;       // intra-row chunk
    const int grp = lane >> 3;      // column subgroup 0..3
    const int g = qb * 8 + warp;    // global query row
    const int n = g & (Nn - 1);     // sequence position (col_ids row)
    const int bh = g >> 11;         // b*H + h
    const unsigned FULL = 0xffffffffu;

    // Lane base inside each row: uint4 index `sub` (line 0) / `8+sub` (line 1).
    const uint4* __restrict__ kb = g_k16 + (size_t)bh * (Nn * ROW_U4) + sub;
    const uint4* __restrict__ vb = g_v16 + (size_t)bh * (Nn * ROW_U4) + sub;

    // q: lane owns dims [8*sub, 8*sub+8) and [64+8*sub, 64+8*sub+8)
    const float4* qrow = reinterpret_cast<const float4*>(q) + (size_t)g * 32;
    float qv[16];
    {
        float4 t0 = qrow[2 * sub];
        float4 t1 = qrow[2 * sub + 1];
        float4 t2 = qrow[16 + 2 * sub];
        float4 t3 = qrow[16 + 2 * sub + 1];
        qv[0] = t0.x;  qv[1] = t0.y;  qv[2]  = t0.z;  qv[3]  = t0.w;
        qv[4] = t1.x;  qv[5] = t1.y;  qv[6]  = t1.z;  qv[7]  = t1.w;
        qv[8] = t2.x;  qv[9] = t2.y;  qv[10] = t2.z;  qv[11] = t2.w;
        qv[12] = t3.x; qv[13] = t3.y; qv[14] = t3.z;  qv[15] = t3.w;
    }

    const int* crow = col_ids + n * Ww;
    const int c0 = crow[lane];         // lane l holds column index l
    const int c1 = crow[lane + 32];    // and column l+32

    // ---- scores: lane (grp,sub) ends with cols 4*sub+grp and 32+4*sub+grp ----
    float sA = score_pass(kb, c0, qv, grp, sub);
    float sB = score_pass(kb, c1, qv, grp, sub);

    // ---- softmax over 64 values distributed 2/lane (order-agnostic) ----
    const float scale = 0.08838834764831843f;   // 1/sqrt(128)
    float a = sA * scale;
    float b = sB * scale;
    float mx = fmaxf(a, b);
#pragma unroll
    for (int o = 16; o > 0; o >>= 1) mx = fmaxf(mx, __shfl_xor_sync(FULL, mx, o));
    const float eA = __expf(a - mx);
    const float eB = __expf(b - mx);
    float sm = eA + eB;
#pragma unroll
    for (int o = 16; o > 0; o >>= 1) sm += __shfl_xor_sync(FULL, sm, o);
    const float inv = __fdividef(1.0f, sm);
    const float pA = eA * inv;   // prob of column 4*sub+grp
    const float pB = eB * inv;   // prob of column 32+4*sub+grp

    // ---- output: group g accumulates columns {4j+g}; lane owns its 16 dims ----
    float acc[16];
#pragma unroll
    for (int i = 0; i < 16; ++i) acc[i] = 0.f;

#pragma unroll
    for (int j = 0; j < 8; ++j) {
        float pw = __shfl_sync(FULL, pA, grp * 8 + j);   // prob of col 4j+grp
        int col  = __shfl_sync(FULL, c0, 4 * j + grp);   // its column index
        const uint4* r = vb + col * ROW_U4;
        uint4 va = r[0];
        uint4 vb4 = r[8];
        accum16(acc, va, vb4, pw);
    }
#pragma unroll
    for (int j = 0; j < 8; ++j) {
        float pw = __shfl_sync(FULL, pB, grp * 8 + j);   // prob of col 32+4j+grp
        int col  = __shfl_sync(FULL, c1, 4 * j + grp);
        const uint4* r = vb + col * ROW_U4;
        uint4 va = r[0];
        uint4 vb4 = r[8];
        accum16(acc, va, vb4, pw);
    }

    // Reduce the 4 groups' partials. acc layout per lane:
    //   acc[0..8)  = dims [8*sub, 8*sub+8)
    //   acc[8..16) = dims [64+8*sub, 64+8*sub+8)
    // fold_step<8,8>: keep half selected by grp&1 (0 -> low dims, 1 -> +64)
    // fold_step<4,16>: keep quarter selected by grp&2 (+0 or +4 within chunk)
    fold_step<8, 8>(acc, (grp & 1) != 0);
    fold_step<4, 16>(acc, (grp & 2) != 0);

    // Lane (grp,sub) now holds 4 summed dims starting at
    //   64*(grp&1) + 8*sub + 4*(grp>>1)   -> float4 index:
    const int u4idx = 16 * (grp & 1) + 2 * sub + (grp >> 1);  // bijection 0..31
    reinterpret_cast<float4*>(out)[(size_t)g * 32 + u4idx] =
        make_float4(acc[0], acc[1], acc[2], acc[3]);
}

// ---------------------------------------------------------------------------
// Launch. Inputs (metadata order): q f32, k f32, v f32, col_ids i32. Out f32.
// ---------------------------------------------------------------------------
extern "C" void kernel_launch(void* const* d_in, const int* in_sizes, int n_in,
                              void* d_out, int out_size) {
    const float* q = (const float*)d_in[0];
    const float* k = (const float*)d_in[1];
    const float* v = (const float*)d_in[2];
    const int* col = (const int*)d_in[3];
    float* out = (float*)d_out;

    (void)cudaFuncSetAttribute(attn_kernel,
                               cudaFuncAttributePreferredSharedMemoryCarveout,
                               cudaSharedmemCarveoutMaxL1);

    cvt_kernel<<<(TOTAL_U4 + 255) / 256, 256>>>((const float4*)k, (const float4*)v);
    attn_kernel<<<NUM_SM * QB_PER_SM, 256>>>(q, col, out);
}

// round 13
// speedup vs baseline: 2.1915x; 1.1127x over previous
#include <cuda_runtime.h>
#include <cuda_fp16.h>

// Problem constants (B,H,N,D,W) = (2,12,2048,128,64)
#define Bb 2
#define Hh 12
#define Nn 2048
#define Dd 128
#define Ww 64

#define BH      (Bb * Hh)          // 24
#define ROWS    (BH * Nn)          // 49152 query rows
#define ROW_U4  (Dd / 8)           // 16 x uint4 (8 fp16 = 16B) per 256B row
#define TOTAL_U4 (ROWS * ROW_U4)

#define NUM_SM   148
#define QB_TOTAL (ROWS / 8)        // 6144 query-blocks (8 queries / CTA, 1 per warp)
#define QB_PER_SM 42

// fp16 copies of K and V (device-global scratch; no runtime allocation)
__device__ uint4 g_k16[TOTAL_U4];
__device__ uint4 g_v16[TOTAL_U4];

__device__ __forceinline__ unsigned pack2(float x, float y) {
    __half2 h = __floats2half2_rn(x, y);
    return *reinterpret_cast<unsigned*>(&h);
}
__device__ __forceinline__ __half2 u2h2(unsigned u) {
    return *reinterpret_cast<const __half2*>(&u);
}
__device__ __forceinline__ float2 h2f2(__half2 h) {
    return __half22float2(h);
}

// ---------------------------------------------------------------------------
// Kernel 1: convert K,V fp32 -> fp16. Each thread: 2 float4 in, 1 uint4 out.
// ---------------------------------------------------------------------------
__global__ void __launch_bounds__(256) cvt_kernel(const float4* __restrict__ k,
                                                  const float4* __restrict__ v) {
    int i = blockIdx.x * blockDim.x + threadIdx.x;
    if (i >= TOTAL_U4) return;
    float4 a0 = k[2 * i], a1 = k[2 * i + 1];
    uint4 u;
    u.x = pack2(a0.x, a0.y); u.y = pack2(a0.z, a0.w);
    u.z = pack2(a1.x, a1.y); u.w = pack2(a1.z, a1.w);
    g_k16[i] = u;
    float4 b0 = v[2 * i], b1 = v[2 * i + 1];
    u.x = pack2(b0.x, b0.y); u.y = pack2(b0.z, b0.w);
    u.z = pack2(b1.x, b1.y); u.w = pack2(b1.z, b1.w);
    g_v16[i] = u;
}

// Butterfly fold step: p has 2H live entries; lanes with hi==true own the top
// half. After the step, p[0..H) holds pairwise-reduced entries.
template <int H, int MASK>
__device__ __forceinline__ void fold_step(float* p, bool hi) {
#pragma unroll
    for (int i = 0; i < H; ++i) {
        float keep = hi ? p[i + H] : p[i];
        float send = hi ? p[i] : p[i + H];
        p[i] = keep + __shfl_xor_sync(0xffffffffu, send, MASK);
    }
}

// fp16 partial dot of 8 fp16 (one uint4) against qh[0..4): depth-3 half2 tree.
// Returns half2 whose two slots each hold a 4-term partial sum.
__device__ __forceinline__ __half2 dot8h(uint4 a, const __half2* qh) {
    __half2 m0 = __hmul2(u2h2(a.x), qh[0]);
    __half2 m1 = __hmul2(u2h2(a.y), qh[1]);
    __half2 m2 = __hmul2(u2h2(a.z), qh[2]);
    __half2 m3 = __hmul2(u2h2(a.w), qh[3]);
    return __hadd2(__hadd2(m0, m1), __hadd2(m2, m3));
}

// One score pass over 32 columns. Lane = (grp in 0..3, sub in 0..7).
// Slot s: group g handles column 4*s+g. Lane `sub` loads uint4 `row + sub`
// (line 0, contiguous across the 8 lanes) and `row + 8 + sub` (line 1):
// every LDG.128 covers full 128B lines -> 2 wavefronts per gathered row.
// 3-step fold within 8-lane groups -> lane (grp,sub) returns the score of
// column 4*sub + grp.
__device__ __forceinline__ float score_pass(const uint4* __restrict__ kb,
                                            int c, const __half2* qh,
                                            int grp, int sub) {
    float p[8];
#pragma unroll
    for (int s = 0; s < 8; ++s) {
        int col = __shfl_sync(0xffffffffu, c, 4 * s + grp);
        const uint4* r = kb + col * ROW_U4;
        uint4 a = r[0];     // dims [8*sub, 8*sub+8)
        uint4 b = r[8];     // dims [64+8*sub, 64+8*sub+8)
        float2 fa = h2f2(dot8h(a, qh));
        float2 fb = h2f2(dot8h(b, qh + 4));
        p[s] = (fa.x + fa.y) + (fb.x + fb.y);
    }
    fold_step<4, 4>(p, (sub & 4) != 0);
    fold_step<2, 2>(p, (sub & 2) != 0);
    fold_step<1, 1>(p, (sub & 1) != 0);
    return p[0];
}

// Paired-column V accumulation for one half2 slot:
// t = v0*pl + v1*ph in fp16, widen once, add into fp32 accumulators.
__device__ __forceinline__ void acc_slot(float& a0, float& a1,
                                         unsigned v0, unsigned v1,
                                         __half2 pl, __half2 ph) {
    __half2 t = __hfma2(u2h2(v1), ph, __hmul2(u2h2(v0), pl));
    float2 f = h2f2(t);
    a0 += f.x;
    a1 += f.y;
}

// ---------------------------------------------------------------------------
// Kernel 2: attention. One warp per query; 8 warps/CTA. Block->query swizzle
// keeps each SM inside one (b,h)'s 1MB fp16 K/V working set for L1 reuse.
// ---------------------------------------------------------------------------
__global__ void __launch_bounds__(256, 4) attn_kernel(const float* __restrict__ q,
                                                      const int* __restrict__ col_ids,
                                                      float* __restrict__ out) {
    int qb = (int)(blockIdx.x % NUM_SM) * QB_PER_SM + (int)(blockIdx.x / NUM_SM);
    if (qb >= QB_TOTAL) return;

    const int warp = threadIdx.x >> 5;
    const unsigned lane = threadIdx.x & 31u;
    const int sub = lane & 7;       // intra-row chunk
    const int grp = lane >> 3;      // column subgroup 0..3
    const int g = qb * 8 + warp;    // global query row
    const int n = g & (Nn - 1);     // sequence position (col_ids row)
    const int bh = g >> 11;         // b*H + h
    const unsigned FULL = 0xffffffffu;

    // Lane base inside each row: uint4 index `sub` (line 0) / `8+sub` (line 1).
    const uint4* __restrict__ kb = g_k16 + (size_t)bh * (Nn * ROW_U4) + sub;
    const uint4* __restrict__ vb = g_v16 + (size_t)bh * (Nn * ROW_U4) + sub;

    // q in fp16: lane owns dims [8*sub, 8*sub+8) and [64+8*sub, 64+8*sub+8)
    const float4* qrow = reinterpret_cast<const float4*>(q) + (size_t)g * 32;
    __half2 qh[8];
    {
        float4 t0 = qrow[2 * sub];
        float4 t1 = qrow[2 * sub + 1];
        float4 t2 = qrow[16 + 2 * sub];
        float4 t3 = qrow[16 + 2 * sub + 1];
        qh[0] = __floats2half2_rn(t0.x, t0.y);
        qh[1] = __floats2half2_rn(t0.z, t0.w);
        qh[2] = __floats2half2_rn(t1.x, t1.y);
        qh[3] = __floats2half2_rn(t1.z, t1.w);
        qh[4] = __floats2half2_rn(t2.x, t2.y);
        qh[5] = __floats2half2_rn(t2.z, t2.w);
        qh[6] = __floats2half2_rn(t3.x, t3.y);
        qh[7] = __floats2half2_rn(t3.z, t3.w);
    }

    const int* crow = col_ids + n * Ww;
    const int c0 = crow[lane];         // lane l holds column index l
    const int c1 = crow[lane + 32];    // and column l+32

    // ---- scores: lane (grp,sub) ends with cols 4*sub+grp and 32+4*sub+grp ----
    float sA = score_pass(kb, c0, qh, grp, sub);
    float sB = score_pass(kb, c1, qh, grp, sub);

    // ---- softmax over 64 values distributed 2/lane (order-agnostic) ----
    const float scale = 0.08838834764831843f;   // 1/sqrt(128)
    float a = sA * scale;
    float b = sB * scale;
    float mx = fmaxf(a, b);
#pragma unroll
    for (int o = 16; o > 0; o >>= 1) mx = fmaxf(mx, __shfl_xor_sync(FULL, mx, o));
    const float eA = __expf(a - mx);
    const float eB = __expf(b - mx);
    float sm = eA + eB;
#pragma unroll
    for (int o = 16; o > 0; o >>= 1) sm += __shfl_xor_sync(FULL, sm, o);
    const float inv = __fdividef(1.0f, sm);
    const float pA = eA * inv;   // prob of column 4*sub+grp
    const float pB = eB * inv;   // prob of column 32+4*sub+grp

    // Pack both probs into one half2 so ONE shuffle moves both per pair.
    __half2 pp = __floats2half2_rn(pA, pB);
    const unsigned ppu = *reinterpret_cast<const unsigned*>(&pp);

    // ---- output: group g accumulates column pairs (4j+g, 32+4j+g) ----
    float acc[16];
#pragma unroll
    for (int i = 0; i < 16; ++i) acc[i] = 0.f;

#pragma unroll
    for (int j = 0; j < 8; ++j) {
        unsigned pv = __shfl_sync(FULL, ppu, grp * 8 + j);   // (p_{4j+g}, p_{32+4j+g})
        int col0 = __shfl_sync(FULL, c0, 4 * j + grp);
        int col1 = __shfl_sync(FULL, c1, 4 * j + grp);
        __half2 pw = u2h2(pv);
        __half2 pl = __low2half2(pw);    // broadcast p of col0
        __half2 ph = __high2half2(pw);   // broadcast p of col1
        const uint4* r0 = vb + col0 * ROW_U4;
        const uint4* r1 = vb + col1 * ROW_U4;
        uint4 a0 = r0[0], b0 = r0[8];
        uint4 a1 = r1[0], b1 = r1[8];
        acc_slot(acc[0],  acc[1],  a0.x, a1.x, pl, ph);
        acc_slot(acc[2],  acc[3],  a0.y, a1.y, pl, ph);
        acc_slot(acc[4],  acc[5],  a0.z, a1.z, pl, ph);
        acc_slot(acc[6],  acc[7],  a0.w, a1.w, pl, ph);
        acc_slot(acc[8],  acc[9],  b0.x, b1.x, pl, ph);
        acc_slot(acc[10], acc[11], b0.y, b1.y, pl, ph);
        acc_slot(acc[12], acc[13], b0.z, b1.z, pl, ph);
        acc_slot(acc[14], acc[15], b0.w, b1.w, pl, ph);
    }

    // Reduce the 4 groups' partials. acc layout per lane:
    //   acc[0..8)  = dims [8*sub, 8*sub+8)
    //   acc[8..16) = dims [64+8*sub, 64+8*sub+8)
    fold_step<8, 8>(acc, (grp & 1) != 0);
    fold_step<4, 16>(acc, (grp & 2) != 0);

    // Lane (grp,sub) holds 4 summed dims starting at 64*(grp&1)+8*sub+4*(grp>>1)
    const int u4idx = 16 * (grp & 1) + 2 * sub + (grp >> 1);  // bijection 0..31
    reinterpret_cast<float4*>(out)[(size_t)g * 32 + u4idx] =
        make_float4(acc[0], acc[1], acc[2], acc[3]);
}

// ---------------------------------------------------------------------------
// Launch. Inputs (metadata order): q f32, k f32, v f32, col_ids i32. Out f32.
// ---------------------------------------------------------------------------
extern "C" void kernel_launch(void* const* d_in, const int* in_sizes, int n_in,
                              void* d_out, int out_size) {
    const float* q = (const float*)d_in[0];
    const float* k = (const float*)d_in[1];
    const float* v = (const float*)d_in[2];
    const int* col = (const int*)d_in[3];
    float* out = (float*)d_out;

    (void)cudaFuncSetAttribute(attn_kernel,
                               cudaFuncAttributePreferredSharedMemoryCarveout,
                               cudaSharedmemCarveoutMaxL1);

    cvt_kernel<<<(TOTAL_U4 + 255) / 256, 256>>>((const float4*)k, (const float4*)v);
    attn_kernel<<<NUM_SM * QB_PER_SM, 256>>>(q, col, out);
}